// round 15
// baseline (speedup 1.0000x reference)
#include <cuda_runtime.h>
#include <math.h>

#define C_DIM   16
#define DK_DIM  8
#define NB_DIM  10
#define NMAX    20000
#define EMAX    50000
#define GMAX    40000
#define AFEAT   4096        // 2 nets * (128 jo * 16 t), T-FASTEST within jo
#define NCH     100         // n-chunks in tensor gemm

// Scratch (device globals — allocation-free; zero-initialized at load)
__device__ float g_A[(size_t)NMAX * AFEAT];   // [n][net][jo][t]
__device__ float g_Whi[AFEAT * 16];           // [f][c] tf32-high
__device__ float g_Wlo[AFEAT * 16];           // [f][c] tf32-low
__device__ float g_xhT[16 * NMAX];            // TILED: [n>>3][c][n&7] tf32-high
__device__ float g_xlT[16 * NMAX];            // TILED: [n>>3][c][n&7] tf32-low
__device__ float g_q[NMAX * DK_DIM];
__device__ float g_expv[EMAX];
__device__ float g_v[EMAX * DK_DIM];
__device__ float g_z[NMAX];
__device__ int   g_count[NMAX];               // MUST be 0 at launch entry
__device__ int   g_rowstart[NMAX];
__device__ int   g_cursor[NMAX];
__device__ int   g_gofs[NMAX];
__device__ int   g_esorted[EMAX];
__device__ int   g_gsrc[GMAX];                // node list (d>0)
__device__ int   g_counters[2];               // [0]=edges, [1]=active nodes

__device__ __forceinline__ float to_tf32(float v) {
    unsigned u;
    asm("cvt.rna.tf32.f32 %0, %1;" : "=r"(u) : "f"(v));
    return __uint_as_float(u);
}

#define MMA1688(d, a, b)                                                      \
    asm volatile(                                                             \
        "mma.sync.aligned.m16n8k8.row.col.f32.tf32.tf32.f32 "                 \
        "{%0,%1,%2,%3}, {%4,%5,%6,%7}, {%8,%9}, {%0,%1,%2,%3};\n"             \
        : "+f"((d)[0]), "+f"((d)[1]), "+f"((d)[2]), "+f"((d)[3])              \
        : "r"(__float_as_uint((a)[0])), "r"(__float_as_uint((a)[1])),         \
          "r"(__float_as_uint((a)[2])), "r"(__float_as_uint((a)[3])),         \
          "r"(__float_as_uint((b)[0])), "r"(__float_as_uint((b)[1])))

#define STS32(addr, val) \
    asm volatile("st.shared.f32 [%0], %1;" :: "r"(addr), "f"(val) : "memory")
#define LDS128A(v, addr) \
    asm volatile("ld.shared.v4.f32 {%0,%1,%2,%3}, [%4];" \
        : "=f"((v).x), "=f"((v).y), "=f"((v).z), "=f"((v).w) : "r"(addr) : "memory")

// ---------------------------------------------------------------------------
// K1: prep (W permute+split t-fastest, x transpose+split tiled, q, zero z/ctr)
//     + hist — one launch.
__global__ void __launch_bounds__(256) prep_hist_kernel(
    const float* __restrict__ Wk2, const float* __restrict__ Wv2,
    const float* __restrict__ x,   const float* __restrict__ Wq,
    const int* __restrict__ esrc, int N, int E) {
    int b = blockIdx.x;
    if (b < 256) {
        int idx = b * 256 + threadIdx.x;          // 65536 = 4096f * 16c
        int c   = idx & 15;
        int f   = idx >> 4;
        int t   = f & 15;                         // t fastest
        int jo  = (f >> 4) & 127;
        int net = f >> 11;
        const float* W = net ? Wv2 : Wk2;
        float w  = W[t * 2048 + c * 128 + jo];
        float hi = to_tf32(w);
        g_Whi[f * 16 + c] = hi;
        g_Wlo[f * 16 + c] = to_tf32(w - hi);
    } else if (b < 1506) {
        int i = (b - 256) * 256 + threadIdx.x;    // N*16
        if (i < N * C_DIM) {
            int n = i >> 4, c = i & 15;
            float v  = x[i];
            float hi = to_tf32(v);
            int ti = (n >> 3) * 128 + c * 8 + (n & 7);
            g_xhT[ti] = hi;
            g_xlT[ti] = to_tf32(v - hi);
        }
    } else if (b < 2131) {
        int i = (b - 1506) * 256 + threadIdx.x;   // N*8
        if (i < N * DK_DIM) {
            int n = i >> 3, o = i & 7;
            float s = 0.f;
#pragma unroll
            for (int c = 0; c < C_DIM; c++) s += x[n * C_DIM + c] * Wq[c * DK_DIM + o];
            g_q[i] = s;
        }
    } else if (b < 2210) {
        int n = (b - 2131) * 256 + threadIdx.x;
        if (n < N) g_z[n] = 0.f;
        if (b == 2131 && threadIdx.x < 2) g_counters[threadIdx.x] = 0;
    } else {
        int e = (b - 2210) * 256 + threadIdx.x;
        if (e < E) atomicAdd(&g_count[esrc[e]], 1);
    }
}

// ---------------------------------------------------------------------------
// K2: assign — block-aggregated offsets for edge slots and node-list slots.
__global__ void __launch_bounds__(256) assign_kernel(int N) {
    __shared__ int s[256];
    __shared__ int sg[256];
    __shared__ int baseE, baseG;
    int t = threadIdx.x;
    int n = blockIdx.x * 256 + t;
    int c  = (n < N) ? g_count[n] : 0;
    int gc = (c > 0) ? 1 : 0;
    s[t] = c; sg[t] = gc;
    __syncthreads();
#pragma unroll
    for (int off = 1; off < 256; off <<= 1) {
        int v  = (t >= off) ? s[t - off]  : 0;
        int vg = (t >= off) ? sg[t - off] : 0;
        __syncthreads();
        s[t] += v; sg[t] += vg;
        __syncthreads();
    }
    if (t == 255) {
        baseE = atomicAdd(&g_counters[0], s[255]);
        baseG = atomicAdd(&g_counters[1], sg[255]);
    }
    __syncthreads();
    if (n < N) {
        int st = baseE + s[t] - c;
        g_rowstart[n] = st;
        g_cursor[n]   = st;
        g_gofs[n]     = baseG + sg[t] - gc;
    }
}

// ---------------------------------------------------------------------------
// K3: sortscatter + node-list write + a_gemm in ONE launch.
// blocks [0,EB): sortscatter; [EB,FB): nodelist; [FB,FB+1600): gemm.
__global__ void __launch_bounds__(256, 3) sort_gemm_kernel(
    const int* __restrict__ esrc, int E, int N, int EB, int FB) {
    int b = blockIdx.x;
    if (b < FB) {
        if (b < EB) {
            int e = b * 256 + threadIdx.x;
            if (e >= E) return;
            int p = atomicAdd(&g_cursor[esrc[e]], 1);
            g_esorted[p] = e;
        } else {
            int n = (b - EB) * 256 + threadIdx.x;
            if (n >= N) return;
            if (g_count[n] > 0) g_gsrc[g_gofs[n]] = n;
        }
        return;
    }

    // ---- a_gemm via 3xTF32 mma.sync (pipelined, hoisted addresses) ----
    __shared__ __align__(16) float sC[8][256];

    int bb   = b - FB;                            // 0..1599
    int tid  = threadIdx.x;
    int w    = tid >> 5;
    int lane = tid & 31;
    int ft   = bb & 15;                           // f-tile of 256
    int chunk = bb >> 4;                          // 0..NCH-1
    int ntiles = (N + 7) >> 3;
    int per = (ntiles + NCH - 1) / NCH;
    int it0 = chunk * per;
    int it1 = it0 + per; if (it1 > ntiles) it1 = ntiles;
    if (it0 >= it1) return;

    int g = lane >> 2, t = lane & 3;
    int f0 = ft * 256 + w * 32;
    float* sCw = sC[w];
    unsigned sbase = (unsigned)__cvta_generic_to_shared(sCw);

    float ahi[2][2][4], alo[2][2][4];
#pragma unroll
    for (int m = 0; m < 2; m++) {
        int fb = f0 + m * 16;
#pragma unroll
        for (int kh = 0; kh < 2; kh++) {
            int c0 = t + 8 * kh;
            ahi[m][kh][0] = g_Whi[(fb + g) * 16 + c0];
            ahi[m][kh][1] = g_Whi[(fb + g + 8) * 16 + c0];
            ahi[m][kh][2] = g_Whi[(fb + g) * 16 + c0 + 4];
            ahi[m][kh][3] = g_Whi[(fb + g + 8) * 16 + c0 + 4];
            alo[m][kh][0] = g_Wlo[(fb + g) * 16 + c0];
            alo[m][kh][1] = g_Wlo[(fb + g + 8) * 16 + c0];
            alo[m][kh][2] = g_Wlo[(fb + g) * 16 + c0 + 4];
            alo[m][kh][3] = g_Wlo[(fb + g + 8) * 16 + c0 + 4];
        }
    }

    unsigned pa[8];
    {
        int na = 2 * t, nb = na + 1;
#pragma unroll
        for (int m = 0; m < 2; m++) {
            int f1 = m * 16 + g, f2 = f1 + 8;
            pa[m * 4 + 0] = sbase + 4 * (na * 32 + ((f1 + 4 * na) & 31));
            pa[m * 4 + 1] = sbase + 4 * (nb * 32 + ((f1 + 4 * nb) & 31));
            pa[m * 4 + 2] = sbase + 4 * (na * 32 + ((f2 + 4 * na) & 31));
            pa[m * 4 + 3] = sbase + 4 * (nb * 32 + ((f2 + 4 * nb) & 31));
        }
    }
    unsigned pl[2];
    float* pg[2];
    int nloc[2];
#pragma unroll
    for (int h = 0; h < 2; h++) {
        int n = (lane >> 3) + 4 * h;
        int q = lane & 7;
        pl[h] = sbase + 4 * (n * 32 + ((q * 4 + 4 * n) & 31));
        nloc[h] = n;
        pg[h] = g_A + (size_t)(it0 * 8 + n) * AFEAT + f0 + q * 4;
    }
    const float* pxh = g_xhT + it0 * 128;
    const float* pxl = g_xlT + it0 * 128;
    int ob0 = t * 8 + g, ob1 = (t + 4) * 8 + g;
    int ob2 = (t + 8) * 8 + g, ob3 = (t + 12) * 8 + g;

    float bhi[2][2], blo[2][2];
    bhi[0][0] = pxh[ob0]; bhi[0][1] = pxh[ob1];
    bhi[1][0] = pxh[ob2]; bhi[1][1] = pxh[ob3];
    blo[0][0] = pxl[ob0]; blo[0][1] = pxl[ob1];
    blo[1][0] = pxl[ob2]; blo[1][1] = pxl[ob3];

#pragma unroll 2
    for (int it = it0; it < it1; it++) {
        float nhi[2][2] = {{0.f,0.f},{0.f,0.f}}, nlo[2][2] = {{0.f,0.f},{0.f,0.f}};
        if (it + 1 < it1) {
            nhi[0][0] = pxh[ob0 + 128]; nhi[0][1] = pxh[ob1 + 128];
            nhi[1][0] = pxh[ob2 + 128]; nhi[1][1] = pxh[ob3 + 128];
            nlo[0][0] = pxl[ob0 + 128]; nlo[0][1] = pxl[ob1 + 128];
            nlo[1][0] = pxl[ob2 + 128]; nlo[1][1] = pxl[ob3 + 128];
        }

        float acc[2][4] = {{0.f,0.f,0.f,0.f},{0.f,0.f,0.f,0.f}};
#pragma unroll
        for (int m = 0; m < 2; m++) {
#pragma unroll
            for (int kh = 0; kh < 2; kh++) {
                MMA1688(acc[m], ahi[m][kh], bhi[kh]);
                MMA1688(acc[m], ahi[m][kh], blo[kh]);
                MMA1688(acc[m], alo[m][kh], bhi[kh]);
            }
        }

        __syncwarp();
        STS32(pa[0], acc[0][0]); STS32(pa[1], acc[0][1]);
        STS32(pa[2], acc[0][2]); STS32(pa[3], acc[0][3]);
        STS32(pa[4], acc[1][0]); STS32(pa[5], acc[1][1]);
        STS32(pa[6], acc[1][2]); STS32(pa[7], acc[1][3]);
        __syncwarp();

        int n0 = it * 8;
#pragma unroll
        for (int h = 0; h < 2; h++) {
            float4 v;
            LDS128A(v, pl[h]);
            int ng = n0 + nloc[h];
            if (ng < N && g_count[ng] > 0) *(float4*)pg[h] = v;  // skip dead rows
            pg[h] += 8 * AFEAT;
        }
        pxh += 128; pxl += 128;

#pragma unroll
        for (int kh = 0; kh < 2; kh++) {
            bhi[kh][0] = nhi[kh][0]; bhi[kh][1] = nhi[kh][1];
            blo[kh][0] = nlo[kh][0]; blo[kh][1] = nlo[kh][1];
        }
    }
}

// ---------------------------------------------------------------------------
// K4 (PROFILED SLOT): edge pass — ONE BLOCK PER SOURCE NODE (d>0).
// 128 threads load the 16 KB A row once; 4 warps loop over the node's edges.
#define PADR 20
__global__ void __launch_bounds__(128) edge_pass_kernel(
    const float* __restrict__ pos,
    const float* __restrict__ Wk1, const float* __restrict__ Wv1,
    const int* __restrict__ edst) {

    __shared__ __align__(16) float sAp[256 * PADR];   // [jo'][t] padded
    __shared__ float hsm[4][32];
    __shared__ float shs[4][16];

    if (blockIdx.x >= g_counters[1]) return;
    int src  = g_gsrc[blockIdx.x];
    int base = g_rowstart[src];
    int d    = g_count[src];

    int tid  = threadIdx.x;
    int warp = tid >> 5;
    int lane = tid & 31;

    // cooperative A row load (coalesced LDG.128) into padded smem
    {
        const float4* Ar = (const float4*)(g_A + (size_t)src * AFEAT);
#pragma unroll
        for (int i = 0; i < 8; i++) {
            int f4 = tid + 128 * i;
            float4 v = Ar[f4];
            int jo = f4 >> 2;
            int t0 = (f4 & 3) * 4;
            *(float4*)&sAp[jo * PADR + t0] = v;
        }
    }
    float psx = pos[src * 3 + 0], psy = pos[src * 3 + 1], psz = pos[src * 3 + 2];
    __syncthreads();

    int o_l = lane & 7;
    for (int i = warp; i < d; i += 4) {
        int e   = g_esorted[base + i];
        int dst = edst[e];

        float vx = psx - pos[dst * 3 + 0];
        float vy = psy - pos[dst * 3 + 1];
        float vz = psz - pos[dst * 3 + 2];
        float r2  = vx * vx + vy * vy + vz * vz;
        float rsh = sqrtf(r2);
        float inv = 1.f / fmaxf(rsh, 1e-9f);
        float ux = vx * inv, uy = vy * inv, uz = vz * inv;
        float r = sqrtf(r2 + 1e-18f);

        if (lane == 0) {
            float xx = ux * ux, yy = uy * uy, zz = uz * uz;
            float* S = shs[warp];
            S[0]  = 1.f;
            S[1]  = 1.7320508f * ux;
            S[2]  = 1.7320508f * uy;
            S[3]  = 1.7320508f * uz;
            S[4]  = 3.8729833f * ux * uy;
            S[5]  = 3.8729833f * uy * uz;
            S[6]  = 1.1180340f * (3.f * zz - 1.f);
            S[7]  = 3.8729833f * ux * uz;
            S[8]  = 1.9364917f * (xx - yy);
            S[9]  = 2.0916501f * uy * (3.f * xx - yy);
            S[10] = 10.2469508f * ux * uy * uz;
            S[11] = 1.6201852f * uy * (5.f * zz - 1.f);
            S[12] = 1.3228757f * uz * (5.f * zz - 3.f);
            S[13] = 1.6201852f * ux * (5.f * zz - 1.f);
            S[14] = 5.1234754f * uz * (xx - yy);
            S[15] = 2.0916501f * ux * (xx - 3.f * yy);
        }
        {
            const float step = 3.5f / 11.f;
            const float EMB_K = 1.14136f * 7.3890561f * 3.16227766f;
            float rs = r / step;
            float emb[NB_DIM];
#pragma unroll
            for (int b = 0; b < NB_DIM; b++) {
                float u = rs - (float)(b + 1);
                float y = 0.f;
                if (fabsf(u) < 1.f) y = expf(-1.f / (1.f - u * u));
                emb[b] = EMB_K * y;
            }
            int net = lane >> 4, t = lane & 15;
            const float* W1 = net ? Wv1 : Wk1;
            float dd = 0.f;
#pragma unroll
            for (int b = 0; b < NB_DIM; b++) dd += emb[b] * W1[b * 16 + t];
            dd *= 0.316227766f;
            hsm[warp][lane] = dd / (1.f + expf(-dd));
        }
        __syncwarp();

        float results[2];
#pragma unroll
        for (int net = 0; net < 2; net++) {
            float4 h0 = *(const float4*)&hsm[warp][net * 16];
            float4 h1 = *(const float4*)&hsm[warp][net * 16 + 4];
            float4 h2 = *(const float4*)&hsm[warp][net * 16 + 8];
            float4 h3 = *(const float4*)&hsm[warp][net * 16 + 12];
            float kp = 0.f;
#pragma unroll
            for (int jj = 0; jj < 4; jj++) {
                const float* col = sAp + (net * 128 + lane + 32 * jj) * PADR;
                float4 a0 = *(const float4*)(col);
                float4 a1 = *(const float4*)(col + 4);
                float4 a2 = *(const float4*)(col + 8);
                float4 a3 = *(const float4*)(col + 12);
                float p = a0.x*h0.x + a0.y*h0.y + a0.z*h0.z + a0.w*h0.w
                        + a1.x*h1.x + a1.y*h1.y + a1.z*h1.z + a1.w*h1.w
                        + a2.x*h2.x + a2.y*h2.y + a2.z*h2.z + a2.w*h2.w
                        + a3.x*h3.x + a3.y*h3.y + a3.z*h3.z + a3.w*h3.w;
                kp += p * shs[warp][(lane >> 3) + 4 * jj];
            }
            kp += __shfl_xor_sync(0xffffffffu, kp, 8);
            kp += __shfl_xor_sync(0xffffffffu, kp, 16);
            results[net] = kp * (1.f / 64.f);
        }

        if (lane < 8) g_v[e * DK_DIM + lane] = results[1];

        float q_o = g_q[dst * DK_DIM + o_l];
        float prod = results[0] * q_o;
        prod += __shfl_xor_sync(0xffffffffu, prod, 1);
        prod += __shfl_xor_sync(0xffffffffu, prod, 2);
        prod += __shfl_xor_sync(0xffffffffu, prod, 4);

        if (lane == 0) {
            float logit = prod * 0.35355339f;
            float tcut = 10.f * (1.f - r * (1.f / 3.5f));
            float cut = (tcut > 0.f) ? expf(-1.f / tcut) : 0.f;
            float ev = cut * expf(logit);
            g_expv[e] = ev;
            atomicAdd(&g_z[dst], ev);
        }
        __syncwarp();
    }
}

// ---------------------------------------------------------------------------
// K5: scatter + re-zero g_count/g_counters for the next replay.
__global__ void __launch_bounds__(256) scatter_clean_kernel(
    const int* __restrict__ edst, float* __restrict__ out, int E, int N, int SB) {
    int b = blockIdx.x;
    if (b < SB) {
        int i = b * 256 + threadIdx.x;
        if (i >= E * DK_DIM) return;
        int e = i >> 3;
        int dst = edst[e];
        float z = g_z[dst];
        if (z == 0.f) z = 1.f;
        float a = g_expv[e] / z;
        atomicAdd(&out[dst * DK_DIM + (i & 7)], sqrtf(a) * g_v[i]);
    } else {
        int n = (b - SB) * 256 + threadIdx.x;
        if (n < N) g_count[n] = 0;
    }
}

// ---------------------------------------------------------------------------
extern "C" void kernel_launch(void* const* d_in, const int* in_sizes, int n_in,
                              void* d_out, int out_size) {
    const float* pos = (const float*)d_in[0];
    const float* x   = (const float*)d_in[1];
    const float* Wq  = (const float*)d_in[2];
    const float* Wk1 = (const float*)d_in[3];
    const float* Wk2 = (const float*)d_in[4];
    const float* Wv1 = (const float*)d_in[5];
    const float* Wv2 = (const float*)d_in[6];
    const int* esrc  = (const int*)d_in[7];
    const int* edst  = (const int*)d_in[8];

    int N = in_sizes[1] / C_DIM;
    int E = in_sizes[7];
    float* out = (float*)d_out;

    cudaMemsetAsync(out, 0, (size_t)out_size * sizeof(float));

    int EB = (E + 255) / 256;                   // 196
    int zb = (N + 255) / 256;                   // 79
    // K1: prep + hist
    prep_hist_kernel<<<2210 + EB, 256>>>(Wk2, Wv2, x, Wq, esrc, N, E);
    // K2: assign
    assign_kernel<<<zb, 256>>>(N);
    // K3: sortscatter + nodelist + a_gemm (overlapped in one launch)
    int FB = EB + zb;
    sort_gemm_kernel<<<FB + 16 * NCH, 256>>>(esrc, E, N, EB, FB);
    // K4 (profiled): edge pass, one block per active node
    edge_pass_kernel<<<N, 128>>>(pos, Wk1, Wv1, edst);
    // K5: scatter + cleanup
    int SB = (E * DK_DIM + 255) / 256;
    scatter_clean_kernel<<<SB + zb, 256>>>(edst, out, E, N, SB);
}

// round 16
// speedup vs baseline: 1.2654x; 1.2654x over previous
#include <cuda_runtime.h>
#include <math.h>

#define C_DIM   16
#define DK_DIM  8
#define NB_DIM  10
#define NMAX    20000
#define EMAX    50000
#define GMAX    40000
#define AFEAT   4096        // 2 nets * (16 t * 128 jo), jo fastest
#define NCH     100         // n-chunks in tensor gemm

// Scratch (device globals — allocation-free)
__device__ float g_A[(size_t)NMAX * AFEAT];   // [n][net][t][jo]
__device__ float g_Whi[AFEAT * 16];           // [f][c] tf32-high
__device__ float g_Wlo[AFEAT * 16];           // [f][c] tf32-low
__device__ float g_xhT[16 * NMAX];            // TILED: [n>>3][c][n&7] tf32-high
__device__ float g_xlT[16 * NMAX];            // TILED: [n>>3][c][n&7] tf32-low
__device__ float g_q[NMAX * DK_DIM];
__device__ float g_expv[EMAX];
__device__ float g_v[EMAX * DK_DIM];
__device__ float g_z[NMAX];
__device__ int   g_count[NMAX];
__device__ int   g_rowstart[NMAX];
__device__ int   g_cursor[NMAX];
__device__ int   g_gofs[NMAX];
__device__ int   g_esorted[EMAX];
__device__ int   g_ginfo[GMAX];               // (base<<3)|cnt
__device__ int   g_gsrc[GMAX];
__device__ int   g_counters[2];               // [0]=edges, [1]=groups

__device__ __forceinline__ float to_tf32(float v) {
    unsigned u;
    asm("cvt.rna.tf32.f32 %0, %1;" : "=r"(u) : "f"(v));
    return __uint_as_float(u);
}

#define MMA1688(d, a, b)                                                      \
    asm volatile(                                                             \
        "mma.sync.aligned.m16n8k8.row.col.f32.tf32.tf32.f32 "                 \
        "{%0,%1,%2,%3}, {%4,%5,%6,%7}, {%8,%9}, {%0,%1,%2,%3};\n"             \
        : "+f"((d)[0]), "+f"((d)[1]), "+f"((d)[2]), "+f"((d)[3])              \
        : "r"(__float_as_uint((a)[0])), "r"(__float_as_uint((a)[1])),         \
          "r"(__float_as_uint((a)[2])), "r"(__float_as_uint((a)[3])),         \
          "r"(__float_as_uint((b)[0])), "r"(__float_as_uint((b)[1])))

#define STS32(addr, val) \
    asm volatile("st.shared.f32 [%0], %1;" :: "r"(addr), "f"(val) : "memory")
#define LDS128A(v, addr) \
    asm volatile("ld.shared.v4.f32 {%0,%1,%2,%3}, [%4];" \
        : "=f"((v).x), "=f"((v).y), "=f"((v).z), "=f"((v).w) : "r"(addr) : "memory")

// ---------------------------------------------------------------------------
// prep: W permute+split, x transpose+split (TILED), q = x@Wq, zeroing.
__global__ void __launch_bounds__(256) prep_kernel(
    const float* __restrict__ Wk2, const float* __restrict__ Wv2,
    const float* __restrict__ x,   const float* __restrict__ Wq, int N) {
    int b = blockIdx.x;
    if (b < 256) {
        int idx = b * 256 + threadIdx.x;          // 65536 = 4096f * 16c
        int c   = idx & 15;
        int f   = idx >> 4;
        int jo  = f & 127;
        int t   = (f >> 7) & 15;
        int net = f >> 11;
        const float* W = net ? Wv2 : Wk2;
        float w  = W[t * 2048 + c * 128 + jo];
        float hi = to_tf32(w);
        g_Whi[f * 16 + c] = hi;
        g_Wlo[f * 16 + c] = to_tf32(w - hi);
    } else if (b < 1506) {
        int i = (b - 256) * 256 + threadIdx.x;    // N*16
        if (i < N * C_DIM) {
            int n = i >> 4, c = i & 15;
            float v  = x[i];
            float hi = to_tf32(v);
            int ti = (n >> 3) * 128 + c * 8 + (n & 7);
            g_xhT[ti] = hi;
            g_xlT[ti] = to_tf32(v - hi);
        }
    } else if (b < 2131) {
        int i = (b - 1506) * 256 + threadIdx.x;   // N*8
        if (i < N * DK_DIM) {
            int n = i >> 3, o = i & 7;
            float s = 0.f;
#pragma unroll
            for (int c = 0; c < C_DIM; c++) s += x[n * C_DIM + c] * Wq[c * DK_DIM + o];
            g_q[i] = s;
        }
    } else {
        int n = (b - 2131) * 256 + threadIdx.x;
        if (n < N) { g_count[n] = 0; g_z[n] = 0.f; }
        if (b == 2131 && threadIdx.x < 2) g_counters[threadIdx.x] = 0;
    }
}

// ---------------------------------------------------------------------------
// a_gemm via 3xTF32 mma.sync — pipelined, hoisted addresses.
__global__ void __launch_bounds__(256, 3) a_gemm_tc_kernel(int N) {
    __shared__ __align__(16) float sC[8][256];

    int tid  = threadIdx.x;
    int w    = tid >> 5;
    int lane = tid & 31;
    int ft   = blockIdx.x;
    int chunk = blockIdx.y;
    int ntiles = (N + 7) >> 3;
    int per = (ntiles + NCH - 1) / NCH;
    int it0 = chunk * per;
    int it1 = it0 + per; if (it1 > ntiles) it1 = ntiles;
    if (it0 >= it1) return;

    int g = lane >> 2, t = lane & 3;
    int f0 = ft * 256 + w * 32;
    float* sCw = sC[w];
    unsigned sbase = (unsigned)__cvta_generic_to_shared(sCw);

    float ahi[2][2][4], alo[2][2][4];
#pragma unroll
    for (int m = 0; m < 2; m++) {
        int fb = f0 + m * 16;
#pragma unroll
        for (int kh = 0; kh < 2; kh++) {
            int c0 = t + 8 * kh;
            ahi[m][kh][0] = g_Whi[(fb + g) * 16 + c0];
            ahi[m][kh][1] = g_Whi[(fb + g + 8) * 16 + c0];
            ahi[m][kh][2] = g_Whi[(fb + g) * 16 + c0 + 4];
            ahi[m][kh][3] = g_Whi[(fb + g + 8) * 16 + c0 + 4];
            alo[m][kh][0] = g_Wlo[(fb + g) * 16 + c0];
            alo[m][kh][1] = g_Wlo[(fb + g + 8) * 16 + c0];
            alo[m][kh][2] = g_Wlo[(fb + g) * 16 + c0 + 4];
            alo[m][kh][3] = g_Wlo[(fb + g + 8) * 16 + c0 + 4];
        }
    }

    unsigned pa[8];
    {
        int na = 2 * t, nb = na + 1;
#pragma unroll
        for (int m = 0; m < 2; m++) {
            int f1 = m * 16 + g, f2 = f1 + 8;
            pa[m * 4 + 0] = sbase + 4 * (na * 32 + ((f1 + 4 * na) & 31));
            pa[m * 4 + 1] = sbase + 4 * (nb * 32 + ((f1 + 4 * nb) & 31));
            pa[m * 4 + 2] = sbase + 4 * (na * 32 + ((f2 + 4 * na) & 31));
            pa[m * 4 + 3] = sbase + 4 * (nb * 32 + ((f2 + 4 * nb) & 31));
        }
    }
    unsigned pl[2];
    float* pg[2];
    int nloc[2];
#pragma unroll
    for (int h = 0; h < 2; h++) {
        int n = (lane >> 3) + 4 * h;
        int q = lane & 7;
        pl[h] = sbase + 4 * (n * 32 + ((q * 4 + 4 * n) & 31));
        nloc[h] = n;
        pg[h] = g_A + (size_t)(it0 * 8 + n) * AFEAT + f0 + q * 4;
    }
    const float* pxh = g_xhT + it0 * 128;
    const float* pxl = g_xlT + it0 * 128;
    int ob0 = t * 8 + g, ob1 = (t + 4) * 8 + g;
    int ob2 = (t + 8) * 8 + g, ob3 = (t + 12) * 8 + g;

    float bhi[2][2], blo[2][2];
    bhi[0][0] = pxh[ob0]; bhi[0][1] = pxh[ob1];
    bhi[1][0] = pxh[ob2]; bhi[1][1] = pxh[ob3];
    blo[0][0] = pxl[ob0]; blo[0][1] = pxl[ob1];
    blo[1][0] = pxl[ob2]; blo[1][1] = pxl[ob3];

#pragma unroll 2
    for (int it = it0; it < it1; it++) {
        float nhi[2][2] = {{0.f,0.f},{0.f,0.f}}, nlo[2][2] = {{0.f,0.f},{0.f,0.f}};
        if (it + 1 < it1) {
            nhi[0][0] = pxh[ob0 + 128]; nhi[0][1] = pxh[ob1 + 128];
            nhi[1][0] = pxh[ob2 + 128]; nhi[1][1] = pxh[ob3 + 128];
            nlo[0][0] = pxl[ob0 + 128]; nlo[0][1] = pxl[ob1 + 128];
            nlo[1][0] = pxl[ob2 + 128]; nlo[1][1] = pxl[ob3 + 128];
        }

        float acc[2][4] = {{0.f,0.f,0.f,0.f},{0.f,0.f,0.f,0.f}};
#pragma unroll
        for (int m = 0; m < 2; m++) {
#pragma unroll
            for (int kh = 0; kh < 2; kh++) {
                MMA1688(acc[m], ahi[m][kh], bhi[kh]);
                MMA1688(acc[m], ahi[m][kh], blo[kh]);
                MMA1688(acc[m], alo[m][kh], bhi[kh]);
            }
        }

        __syncwarp();
        STS32(pa[0], acc[0][0]); STS32(pa[1], acc[0][1]);
        STS32(pa[2], acc[0][2]); STS32(pa[3], acc[0][3]);
        STS32(pa[4], acc[1][0]); STS32(pa[5], acc[1][1]);
        STS32(pa[6], acc[1][2]); STS32(pa[7], acc[1][3]);
        __syncwarp();

        int n0 = it * 8;
#pragma unroll
        for (int h = 0; h < 2; h++) {
            float4 v;
            LDS128A(v, pl[h]);
            if (n0 + nloc[h] < N) *(float4*)pg[h] = v;
            pg[h] += 8 * AFEAT;
        }
        pxh += 128; pxl += 128;

#pragma unroll
        for (int kh = 0; kh < 2; kh++) {
            bhi[kh][0] = nhi[kh][0]; bhi[kh][1] = nhi[kh][1];
            blo[kh][0] = nlo[kh][0]; blo[kh][1] = nlo[kh][1];
        }
    }
}

// ---------------------------------------------------------------------------
__global__ void hist_kernel(const int* __restrict__ esrc, int E) {
    int e = blockIdx.x * blockDim.x + threadIdx.x;
    if (e < E) atomicAdd(&g_count[esrc[e]], 1);
}

__global__ void __launch_bounds__(256) assign_kernel(int N) {
    __shared__ int s[256];
    __shared__ int sg[256];
    __shared__ int baseE, baseG;
    int t = threadIdx.x;
    int n = blockIdx.x * 256 + t;
    int c  = (n < N) ? g_count[n] : 0;
    int gc = (c + 3) >> 2;
    s[t] = c; sg[t] = gc;
    __syncthreads();
#pragma unroll
    for (int off = 1; off < 256; off <<= 1) {
        int v  = (t >= off) ? s[t - off]  : 0;
        int vg = (t >= off) ? sg[t - off] : 0;
        __syncthreads();
        s[t] += v; sg[t] += vg;
        __syncthreads();
    }
    if (t == 255) {
        baseE = atomicAdd(&g_counters[0], s[255]);
        baseG = atomicAdd(&g_counters[1], sg[255]);
    }
    __syncthreads();
    if (n < N) {
        int st = baseE + s[t] - c;
        g_rowstart[n] = st;
        g_cursor[n]   = st;
        g_gofs[n]     = baseG + sg[t] - gc;
    }
}

// fused: sortscatter + groupwrite
__global__ void __launch_bounds__(256) fuse2_kernel(
    const int* __restrict__ esrc, int E, int N, int EB) {
    int b = blockIdx.x;
    if (b < EB) {
        int e = b * 256 + threadIdx.x;
        if (e >= E) return;
        int p = atomicAdd(&g_cursor[esrc[e]], 1);
        g_esorted[p] = e;
    } else {
        int n = (b - EB) * 256 + threadIdx.x;
        if (n >= N) return;
        int d = g_count[n];
        if (d == 0) return;
        int base = g_rowstart[n];
        int go   = g_gofs[n];
        int ng   = (d + 3) >> 2;
        for (int i = 0; i < ng; i++) {
            int cnt = d - 4 * i; if (cnt > 4) cnt = 4;
            g_ginfo[go + i] = ((base + 4 * i) << 3) | cnt;
            g_gsrc[go + i]  = n;
        }
    }
}

// ---------------------------------------------------------------------------
// edge pass: one 128-thread block per group (<=4 edges, same src).
// A row copied via cp.async (no register staging); the per-edge geometry /
// SH / radial-fcnet math executes WHILE the copy is in flight, hiding the
// DRAM latency. Then wait + contract from smem.
__global__ void __launch_bounds__(128) edge_pass_kernel(
    const float* __restrict__ pos,
    const float* __restrict__ Wk1, const float* __restrict__ Wv1,
    const int* __restrict__ edst) {

    __shared__ __align__(16) float sA[AFEAT];   // [net][t][jo]
    __shared__ float hsm[4][32];
    __shared__ float shs[4][16];

    if (blockIdx.x >= g_counters[1]) return;
    int info = g_ginfo[blockIdx.x];
    int src  = g_gsrc[blockIdx.x];
    int base = info >> 3;
    int cnt  = info & 7;

    int tid  = threadIdx.x;
    int warp = tid >> 5;
    int lane = tid & 31;

    // issue async A-row copy: 1024 x 16B, 8 per thread, no registers
    {
        unsigned sA32 = (unsigned)__cvta_generic_to_shared(sA);
        const float4* Ar = (const float4*)(g_A + (size_t)src * AFEAT);
#pragma unroll
        for (int i = 0; i < 8; i++) {
            asm volatile("cp.async.cg.shared.global [%0], [%1], 16;" ::
                "r"(sA32 + (unsigned)((tid + 128 * i) * 16)),
                "l"(Ar + tid + 128 * i) : "memory");
        }
        asm volatile("cp.async.commit_group;" ::: "memory");
    }

    // row-independent per-edge work overlaps the copy
    int e = -1, dst = 0;
    float r = 0.f;
    if (warp < cnt) {
        e   = g_esorted[base + warp];
        dst = edst[e];

        float vx = pos[src * 3 + 0] - pos[dst * 3 + 0];
        float vy = pos[src * 3 + 1] - pos[dst * 3 + 1];
        float vz = pos[src * 3 + 2] - pos[dst * 3 + 2];
        float r2  = vx * vx + vy * vy + vz * vz;
        float rsh = sqrtf(r2);
        float inv = 1.f / fmaxf(rsh, 1e-9f);
        float ux = vx * inv, uy = vy * inv, uz = vz * inv;
        r = sqrtf(r2 + 1e-18f);

        if (lane == 0) {
            float xx = ux * ux, yy = uy * uy, zz = uz * uz;
            float* S = shs[warp];
            S[0]  = 1.f;
            S[1]  = 1.7320508f * ux;
            S[2]  = 1.7320508f * uy;
            S[3]  = 1.7320508f * uz;
            S[4]  = 3.8729833f * ux * uy;
            S[5]  = 3.8729833f * uy * uz;
            S[6]  = 1.1180340f * (3.f * zz - 1.f);
            S[7]  = 3.8729833f * ux * uz;
            S[8]  = 1.9364917f * (xx - yy);
            S[9]  = 2.0916501f * uy * (3.f * xx - yy);
            S[10] = 10.2469508f * ux * uy * uz;
            S[11] = 1.6201852f * uy * (5.f * zz - 1.f);
            S[12] = 1.3228757f * uz * (5.f * zz - 3.f);
            S[13] = 1.6201852f * ux * (5.f * zz - 1.f);
            S[14] = 5.1234754f * uz * (xx - yy);
            S[15] = 2.0916501f * ux * (xx - 3.f * yy);
        }
        {
            const float step = 3.5f / 11.f;
            const float EMB_K = 1.14136f * 7.3890561f * 3.16227766f;
            float rs = r / step;
            float emb[NB_DIM];
#pragma unroll
            for (int b = 0; b < NB_DIM; b++) {
                float u = rs - (float)(b + 1);
                float y = 0.f;
                if (fabsf(u) < 1.f) y = expf(-1.f / (1.f - u * u));
                emb[b] = EMB_K * y;
            }
            int net = lane >> 4, t = lane & 15;
            const float* W1 = net ? Wv1 : Wk1;
            float d = 0.f;
#pragma unroll
            for (int b = 0; b < NB_DIM; b++) d += emb[b] * W1[b * 16 + t];
            d *= 0.316227766f;
            hsm[warp][lane] = d / (1.f + expf(-d));
        }
    }

    asm volatile("cp.async.wait_group 0;" ::: "memory");
    __syncthreads();

    if (warp < cnt) {
        int o_l = lane & 7;
        float results[2];
#pragma unroll
        for (int net = 0; net < 2; net++) {
            const float* An = sA + net * 2048;
            float hr[16];
#pragma unroll
            for (int t = 0; t < 16; t++) hr[t] = hsm[warp][net * 16 + t];
            float kp = 0.f;
#pragma unroll
            for (int jj = 0; jj < 4; jj++) {
                const float* col = An + lane + 32 * jj;
                float p = 0.f;
#pragma unroll
                for (int t = 0; t < 16; t++) p += col[t * 128] * hr[t];
                kp += p * shs[warp][(lane >> 3) + 4 * jj];
            }
            kp += __shfl_xor_sync(0xffffffffu, kp, 8);
            kp += __shfl_xor_sync(0xffffffffu, kp, 16);
            results[net] = kp * (1.f / 64.f);
        }

        if (lane < 8) g_v[e * DK_DIM + lane] = results[1];

        float q_o = g_q[dst * DK_DIM + o_l];
        float prod = results[0] * q_o;
        prod += __shfl_xor_sync(0xffffffffu, prod, 1);
        prod += __shfl_xor_sync(0xffffffffu, prod, 2);
        prod += __shfl_xor_sync(0xffffffffu, prod, 4);

        if (lane == 0) {
            float logit = prod * 0.35355339f;
            float tcut = 10.f * (1.f - r * (1.f / 3.5f));
            float cut = (tcut > 0.f) ? expf(-1.f / tcut) : 0.f;
            float ev = cut * expf(logit);
            g_expv[e] = ev;
            atomicAdd(&g_z[dst], ev);
        }
    }
}

// ---------------------------------------------------------------------------
__global__ void scatter_kernel(const int* __restrict__ edst,
                               float* __restrict__ out, int E) {
    int i = blockIdx.x * blockDim.x + threadIdx.x;
    if (i >= E * DK_DIM) return;
    int e = i >> 3;
    int dst = edst[e];
    float z = g_z[dst];
    if (z == 0.f) z = 1.f;
    float a = g_expv[e] / z;
    float w = sqrtf(a);
    atomicAdd(&out[dst * DK_DIM + (i & 7)], w * g_v[i]);
}

// ---------------------------------------------------------------------------
extern "C" void kernel_launch(void* const* d_in, const int* in_sizes, int n_in,
                              void* d_out, int out_size) {
    const float* pos = (const float*)d_in[0];
    const float* x   = (const float*)d_in[1];
    const float* Wq  = (const float*)d_in[2];
    const float* Wk1 = (const float*)d_in[3];
    const float* Wk2 = (const float*)d_in[4];
    const float* Wv1 = (const float*)d_in[5];
    const float* Wv2 = (const float*)d_in[6];
    const int* esrc  = (const int*)d_in[7];
    const int* edst  = (const int*)d_in[8];

    int N = in_sizes[1] / C_DIM;
    int E = in_sizes[7];
    float* out = (float*)d_out;

    cudaMemsetAsync(out, 0, (size_t)out_size * sizeof(float));

    int xb = (N * C_DIM + 255) / 256;           // 1250
    int qb = (N * DK_DIM + 255) / 256;          // 625
    int zb = (N + 255) / 256;                   // 79
    prep_kernel<<<256 + xb + qb + zb, 256>>>(Wk2, Wv2, x, Wq, N);

    hist_kernel<<<(E + 255) / 256, 256>>>(esrc, E);
    assign_kernel<<<zb, 256>>>(N);

    dim3 gg(16, NCH);
    a_gemm_tc_kernel<<<gg, 256>>>(N);

    int EB = (E + 255) / 256;
    fuse2_kernel<<<EB + zb, 256>>>(esrc, E, N, EB);

    int maxgroups = E / 4 + N;
    edge_pass_kernel<<<maxgroups, 128>>>(pos, Wk1, Wv1, edst);
    scatter_kernel<<<(E * DK_DIM + 255) / 256, 256>>>(edst, out, E);
}